// round 6
// baseline (speedup 1.0000x reference)
#include <cuda_runtime.h>
#include <cuda_bf16.h>
#include <cstdint>

#define ROWS 4096
#define COLS 11008
#define RANK 32
#define GROUPS_PER_ROW 1376   // COLS/8
#define I_SPLIT 2048          // i >= 2048 -> codebook 1

#define TI 128
#define TJ 128
#define THREADS 256

// smem strides (conflict-free by construction)
#define AS_STRIDE 40          // bf16
#define BS_STRIDE 40          // bf16
#define CBS_STRIDE 10         // floats per padded codebook entry (EVEN: float2 gathers stay 8B-aligned)
#define CODES_STRIDE 17       // ints
#define OS_STRIDE 36          // floats (36 mod 32 = 4 -> staging bank = 4*rfrag + q, bijective)

#define AS_BYTES (TI * AS_STRIDE * 2)             // 10240
#define BS_BYTES (TJ * BS_STRIDE * 2)             // 10240
#define CBS_BYTES (512 * CBS_STRIDE * 4)          // 20480
#define CODES_BYTES (TI * CODES_STRIDE * 4)       // 8704
#define OS_BYTES (TI * OS_STRIDE * 4)             // 18432
#define SMEM_TOTAL (AS_BYTES + BS_BYTES + CBS_BYTES + CODES_BYTES + OS_BYTES)  // 68096

__global__ __launch_bounds__(THREADS, 3)
void qw_fused3_kernel(const float* __restrict__ codebooks,  // (2,256,8)
                      const int*   __restrict__ codes,      // flat
                      const float* __restrict__ scales,     // (11008,)
                      const float* __restrict__ L,          // (4096,32)
                      const float* __restrict__ R,          // (32,11008)
                      float*       __restrict__ out)        // (4096,11008)
{
    extern __shared__ char smem[];
    __nv_bfloat16* As      = reinterpret_cast<__nv_bfloat16*>(smem);
    __nv_bfloat16* Bs      = reinterpret_cast<__nv_bfloat16*>(smem + AS_BYTES);
    float*         cbs     = reinterpret_cast<float*>(smem + AS_BYTES + BS_BYTES);
    int*           codes_s = reinterpret_cast<int*>(smem + AS_BYTES + BS_BYTES + CBS_BYTES);
    float*         Os      = reinterpret_cast<float*>(smem + AS_BYTES + BS_BYTES + CBS_BYTES + CODES_BYTES);

    const int tid = threadIdx.x;
    const int wid = tid >> 5;
    const int lid = tid & 31;
    const int i0  = blockIdx.y * TI;
    const int j0  = blockIdx.x * TJ;

    // ---- stage codebooks, stride-10 padded (float2 copies, aligned) ----
    #pragma unroll
    for (int e = tid; e < 512; e += THREADS) {
        const float2* src = reinterpret_cast<const float2*>(codebooks + e * 8);
        float2*       dst = reinterpret_cast<float2*>(cbs + e * CBS_STRIDE);
        dst[0] = src[0]; dst[1] = src[1]; dst[2] = src[2]; dst[3] = src[3];
    }
    // ---- stage A = L tile [128 x 32] bf16 ----
    #pragma unroll
    for (int idx = tid; idx < TI * RANK; idx += THREADS) {
        int row = idx >> 5, k = idx & 31;
        As[row * AS_STRIDE + k] = __float2bfloat16(L[(i0 + row) * RANK + k]);
    }
    // ---- stage B = R^T tile [128n x 32k] bf16 ----
    #pragma unroll
    for (int idx = tid; idx < TJ * RANK; idx += THREADS) {
        int k = idx >> 7, n = idx & 127;
        Bs[n * BS_STRIDE + k] = __float2bfloat16(R[k * COLS + j0 + n]);
    }
    // ---- stage codes tile [128 rows x 16 groups] ----
    #pragma unroll
    for (int idx = tid; idx < TI * 16; idx += THREADS) {
        int row = idx >> 4, t = idx & 15;
        codes_s[row * CODES_STRIDE + t] =
            codes[(i0 + row) * GROUPS_PER_ROW + (j0 >> 3) + t];
    }
    __syncthreads();

    // ---- fragment identity ----
    const int rfrag = lid >> 2;
    const int q     = lid & 3;
    const int r0    = wid * 16 + rfrag;
    const int r1    = r0 + 8;

    // A fragments (whole K=32, loaded once, conflict-free)
    uint32_t a0 = *reinterpret_cast<const uint32_t*>(&As[r0 * AS_STRIDE + 2 * q]);
    uint32_t a1 = *reinterpret_cast<const uint32_t*>(&As[r1 * AS_STRIDE + 2 * q]);
    uint32_t a2 = *reinterpret_cast<const uint32_t*>(&As[r0 * AS_STRIDE + 2 * q + 8]);
    uint32_t a3 = *reinterpret_cast<const uint32_t*>(&As[r1 * AS_STRIDE + 2 * q + 8]);
    uint32_t a4 = *reinterpret_cast<const uint32_t*>(&As[r0 * AS_STRIDE + 16 + 2 * q]);
    uint32_t a5 = *reinterpret_cast<const uint32_t*>(&As[r1 * AS_STRIDE + 16 + 2 * q]);
    uint32_t a6 = *reinterpret_cast<const uint32_t*>(&As[r0 * AS_STRIDE + 24 + 2 * q]);
    uint32_t a7 = *reinterpret_cast<const uint32_t*>(&As[r1 * AS_STRIDE + 24 + 2 * q]);

    const int gi0 = i0 + r0;
    const int gi1 = i0 + r1;
    const float* cb0 = cbs + ((gi0 >= I_SPLIT) ? 256 * CBS_STRIDE : 0);
    const float* cb1 = cbs + ((gi1 >= I_SPLIT) ? 256 * CBS_STRIDE : 0);

    const unsigned base0 = (unsigned)gi0 * COLS + (unsigned)j0;
    const unsigned base1 = (unsigned)gi1 * COLS + (unsigned)j0;
    const int sidx0 = (int)(base0 >> 12);
    const int sidx1 = (int)(base1 >> 12);
    const int tB0 = (int)((4096u - (base0 & 4095u) + 7u) >> 3);
    const int tB1 = (int)((4096u - (base1 & 4095u) + 7u) >> 3);
    const float sLo0 = __ldg(&scales[sidx0]);
    const float sHi0 = __ldg(&scales[(sidx0 + 1 < COLS) ? sidx0 + 1 : COLS - 1]);
    const float sLo1 = __ldg(&scales[sidx1]);
    const float sHi1 = __ldg(&scales[(sidx1 + 1 < COLS) ? sidx1 + 1 : COLS - 1]);

    const int crow0 = r0 * CODES_STRIDE;
    const int crow1 = r1 * CODES_STRIDE;

    // drain identity: warp covers 4 sub-rows x 32 cols per pass
    const int e_row_in_w = lid >> 3;          // 0..3
    const int e_c4       = lid & 7;           // float4 index within 32-col chunk
    const int e_f        = lid & 1;           // f-half of group

    #pragma unroll
    for (int chunk = 0; chunk < 4; chunk++) {
        // ---- 4 fused MMA+dequant iterations, staged to Os (conflict-free STS) ----
        #pragma unroll
        for (int tt = 0; tt < 4; tt++) {
            const int t = chunk * 4 + tt;
            const int nb = (t * 8 + rfrag) * BS_STRIDE;
            uint32_t b0 = *reinterpret_cast<const uint32_t*>(&Bs[nb + 2 * q]);
            uint32_t b1 = *reinterpret_cast<const uint32_t*>(&Bs[nb + 2 * q + 8]);
            uint32_t b2 = *reinterpret_cast<const uint32_t*>(&Bs[nb + 16 + 2 * q]);
            uint32_t b3 = *reinterpret_cast<const uint32_t*>(&Bs[nb + 16 + 2 * q + 8]);

            float c0 = 0.f, c1 = 0.f, c2 = 0.f, c3 = 0.f;
            asm volatile(
                "mma.sync.aligned.m16n8k16.row.col.f32.bf16.bf16.f32 "
                "{%0,%1,%2,%3}, {%4,%5,%6,%7}, {%8,%9}, {%0,%1,%2,%3};"
                : "+f"(c0), "+f"(c1), "+f"(c2), "+f"(c3)
                : "r"(a0), "r"(a1), "r"(a2), "r"(a3), "r"(b0), "r"(b1));
            asm volatile(
                "mma.sync.aligned.m16n8k16.row.col.f32.bf16.bf16.f32 "
                "{%0,%1,%2,%3}, {%4,%5,%6,%7}, {%8,%9}, {%0,%1,%2,%3};"
                : "+f"(c0), "+f"(c1), "+f"(c2), "+f"(c3)
                : "r"(a4), "r"(a5), "r"(a6), "r"(a7), "r"(b2), "r"(b3));

            const int code0 = codes_s[crow0 + t];
            const int code1 = codes_s[crow1 + t];
            const float2 e0 = *reinterpret_cast<const float2*>(cb0 + code0 * CBS_STRIDE + 2 * q);
            const float2 e1 = *reinterpret_cast<const float2*>(cb1 + code1 * CBS_STRIDE + 2 * q);
            const float s0 = (t >= tB0) ? sHi0 : sLo0;
            const float s1 = (t >= tB1) ? sHi1 : sLo1;

            // permuted staging: value (row, q, f) -> Os[row][tt*8 + q + 4f]
            const int cc = tt * 8 + q;
            Os[r0 * OS_STRIDE + cc]     = fmaf(e0.x, s0, c0);   // f=0
            Os[r0 * OS_STRIDE + cc + 4] = fmaf(e0.y, s0, c1);   // f=1
            Os[r1 * OS_STRIDE + cc]     = fmaf(e1.x, s1, c2);
            Os[r1 * OS_STRIDE + cc + 4] = fmaf(e1.y, s1, c3);
        }
        __syncthreads();

        // ---- drain Os chunk: conflict-free LDS.128 + 2 SHFL + coalesced STG.128 ----
        #pragma unroll
        for (int p = 0; p < 4; p++) {
            const int row = p * 32 + wid * 4 + e_row_in_w;
            const float4 v = *reinterpret_cast<const float4*>(&Os[row * OS_STRIDE + 4 * e_c4]);
            float t0 = e_f ? v.x : v.z;
            float t1 = e_f ? v.y : v.w;
            float s0 = __shfl_xor_sync(0xFFFFFFFF, t0, 1);
            float s1 = __shfl_xor_sync(0xFFFFFFFF, t1, 1);
            float4 o;
            if (e_f == 0) { o.x = v.x; o.y = s0; o.z = v.y; o.w = s1; }
            else          { o.x = s0;  o.y = v.z; o.z = s1; o.w = v.w; }

            const unsigned f = (unsigned)(i0 + row) * COLS
                             + (unsigned)(j0 + chunk * 32 + 4 * e_c4);
            *reinterpret_cast<float4*>(&out[f]) = o;
        }
        __syncthreads();
    }
}

extern "C" void kernel_launch(void* const* d_in, const int* in_sizes, int n_in,
                              void* d_out, int out_size) {
    const float* codebooks = (const float*)d_in[0];
    const int*   codes     = (const int*)  d_in[1];
    const float* scales    = (const float*)d_in[2];
    const float* L         = (const float*)d_in[3];
    const float* R         = (const float*)d_in[4];
    float*       out       = (float*)d_out;

    cudaFuncSetAttribute(qw_fused3_kernel,
                         cudaFuncAttributeMaxDynamicSharedMemorySize, SMEM_TOTAL);

    dim3 grid(COLS / TJ, ROWS / TI);   // (86, 32)
    qw_fused3_kernel<<<grid, THREADS, SMEM_TOTAL>>>(codebooks, codes, scales, L, R, out);
}

// round 7
// speedup vs baseline: 1.1616x; 1.1616x over previous
#include <cuda_runtime.h>
#include <cuda_bf16.h>
#include <cstdint>

#define ROWS 4096
#define COLS 11008
#define RANK 32
#define GROUPS_PER_ROW 1376   // COLS/8
#define I_SPLIT_BY 16         // blockIdx.y >= 16 -> codebook 1

#define TI 128
#define TJ 128
#define THREADS 256

#define BS_STRIDE 40          // bf16 (conflict-free B frag loads)
#define CBS_STRIDE 10         // floats (even -> 8B-aligned float2 gathers)
#define CODES_STRIDE 17       // ints
#define OB_STRIDE 68          // floats per staged row: 64 data + 4 pad; 272B = 16B-mult, bank offset 4

#define BS_BYTES (TJ * BS_STRIDE * 2)          // 10240
#define CBS_BYTES (256 * CBS_STRIDE * 4)       // 10240
#define CODES_BYTES (TI * CODES_STRIDE * 4)    // 8704
#define OB_WARP_FLOATS (16 * OB_STRIDE)        // 1088
#define OB_BYTES (8 * OB_WARP_FLOATS * 4)      // 34816
#define SMEM_TOTAL (BS_BYTES + CBS_BYTES + CODES_BYTES + OB_BYTES)  // 64000

static __device__ __forceinline__ uint32_t smem_u32(const void* p) {
    uint32_t a;
    asm("{ .reg .u64 t; cvta.to.shared.u64 t, %1; cvt.u32.u64 %0, t; }" : "=r"(a) : "l"(p));
    return a;
}
static __device__ __forceinline__ uint32_t pk_bf16x2(float2 v) {
    uint32_t r;
    asm("cvt.rn.bf16x2.f32 %0, %1, %2;" : "=r"(r) : "f"(v.y), "f"(v.x));
    return r;
}

__global__ __launch_bounds__(THREADS, 3)
void qw_tma_kernel(const float* __restrict__ codebooks,  // (2,256,8)
                   const int*   __restrict__ codes,      // flat
                   const float* __restrict__ scales,     // (11008,)
                   const float* __restrict__ L,          // (4096,32)
                   const float* __restrict__ R,          // (32,11008)
                   float*       __restrict__ out)        // (4096,11008)
{
    extern __shared__ __align__(16) char smem[];
    __nv_bfloat16* Bs      = reinterpret_cast<__nv_bfloat16*>(smem);
    float*         cbs     = reinterpret_cast<float*>(smem + BS_BYTES);
    int*           codes_s = reinterpret_cast<int*>(smem + BS_BYTES + CBS_BYTES);
    float*         obuf    = reinterpret_cast<float*>(smem + BS_BYTES + CBS_BYTES + CODES_BYTES);

    const int tid = threadIdx.x;
    const int wid = tid >> 5;
    const int lid = tid & 31;
    const int i0  = blockIdx.y * TI;
    const int j0  = blockIdx.x * TJ;

    // ---- stage ONLY this CTA's codebook (rows are all on one side of the split) ----
    {
        const float* cb_src = codebooks + ((blockIdx.y >= I_SPLIT_BY) ? 2048 : 0);
        for (int e = tid; e < 256; e += THREADS) {
            const float2* s = reinterpret_cast<const float2*>(cb_src + e * 8);
            float2*       d = reinterpret_cast<float2*>(cbs + e * CBS_STRIDE);
            d[0] = s[0]; d[1] = s[1]; d[2] = s[2]; d[3] = s[3];
        }
    }
    // ---- stage B = R^T tile [128n x 32k] bf16 ----
    #pragma unroll
    for (int idx = tid; idx < TJ * RANK; idx += THREADS) {
        int k = idx >> 7, n = idx & 127;
        Bs[n * BS_STRIDE + k] = __float2bfloat16(R[k * COLS + j0 + n]);
    }
    // ---- stage codes tile [128 rows x 16 groups] ----
    #pragma unroll
    for (int idx = tid; idx < TI * 16; idx += THREADS) {
        int row = idx >> 4, t = idx & 15;
        codes_s[row * CODES_STRIDE + t] =
            codes[(i0 + row) * GROUPS_PER_ROW + (j0 >> 3) + t];
    }
    __syncthreads();

    // ---- fragment identity ----
    const int rfrag = lid >> 2;
    const int q     = lid & 3;
    const int r0    = wid * 16 + rfrag;
    const int r1    = r0 + 8;
    const int gi0   = i0 + r0;
    const int gi1   = i0 + r1;

    // ---- A fragments straight from gmem (L is 512KB -> L2-hot) ----
    const float* L0 = L + (size_t)gi0 * RANK;
    const float* L1 = L + (size_t)gi1 * RANK;
    uint32_t a0 = pk_bf16x2(*reinterpret_cast<const float2*>(L0 + 2 * q));
    uint32_t a1 = pk_bf16x2(*reinterpret_cast<const float2*>(L1 + 2 * q));
    uint32_t a2 = pk_bf16x2(*reinterpret_cast<const float2*>(L0 + 2 * q + 8));
    uint32_t a3 = pk_bf16x2(*reinterpret_cast<const float2*>(L1 + 2 * q + 8));
    uint32_t a4 = pk_bf16x2(*reinterpret_cast<const float2*>(L0 + 16 + 2 * q));
    uint32_t a5 = pk_bf16x2(*reinterpret_cast<const float2*>(L1 + 16 + 2 * q));
    uint32_t a6 = pk_bf16x2(*reinterpret_cast<const float2*>(L0 + 24 + 2 * q));
    uint32_t a7 = pk_bf16x2(*reinterpret_cast<const float2*>(L1 + 24 + 2 * q));

    const unsigned base0 = (unsigned)gi0 * COLS + (unsigned)j0;
    const unsigned base1 = (unsigned)gi1 * COLS + (unsigned)j0;
    const int sidx0 = (int)(base0 >> 12);
    const int sidx1 = (int)(base1 >> 12);
    const int tB0 = (int)((4096u - (base0 & 4095u) + 7u) >> 3);
    const int tB1 = (int)((4096u - (base1 & 4095u) + 7u) >> 3);
    const float sLo0 = __ldg(&scales[sidx0]);
    const float sHi0 = __ldg(&scales[(sidx0 + 1 < COLS) ? sidx0 + 1 : COLS - 1]);
    const float sLo1 = __ldg(&scales[sidx1]);
    const float sHi1 = __ldg(&scales[(sidx1 + 1 < COLS) ? sidx1 + 1 : COLS - 1]);

    const int crow0 = r0 * CODES_STRIDE;
    const int crow1 = r1 * CODES_STRIDE;

    float* ob = obuf + wid * OB_WARP_FLOATS;
    const uint32_t ob_sm = smem_u32(ob);

    // row this lane drains via TMA (lanes 0..15)
    const int  drow  = lid;                               // local row 0..15
    const unsigned gdst_row = (unsigned)(i0 + wid * 16 + drow) * COLS + (unsigned)j0;

    #pragma unroll
    for (int ch = 0; ch < 2; ch++) {
        // recycle staging buffer: wait until prior chunk's TMA has READ the smem
        if (ch == 1) {
            asm volatile("cp.async.bulk.wait_group.read 0;" ::: "memory");
            __syncwarp();
        }

        #pragma unroll
        for (int tt = 0; tt < 8; tt++) {
            const int t = ch * 8 + tt;
            const int nb = (t * 8 + rfrag) * BS_STRIDE;
            uint32_t b0 = *reinterpret_cast<const uint32_t*>(&Bs[nb + 2 * q]);
            uint32_t b1 = *reinterpret_cast<const uint32_t*>(&Bs[nb + 2 * q + 8]);
            uint32_t b2 = *reinterpret_cast<const uint32_t*>(&Bs[nb + 16 + 2 * q]);
            uint32_t b3 = *reinterpret_cast<const uint32_t*>(&Bs[nb + 16 + 2 * q + 8]);

            float c0 = 0.f, c1 = 0.f, c2 = 0.f, c3 = 0.f;
            asm volatile(
                "mma.sync.aligned.m16n8k16.row.col.f32.bf16.bf16.f32 "
                "{%0,%1,%2,%3}, {%4,%5,%6,%7}, {%8,%9}, {%0,%1,%2,%3};"
                : "+f"(c0), "+f"(c1), "+f"(c2), "+f"(c3)
                : "r"(a0), "r"(a1), "r"(a2), "r"(a3), "r"(b0), "r"(b1));
            asm volatile(
                "mma.sync.aligned.m16n8k16.row.col.f32.bf16.bf16.f32 "
                "{%0,%1,%2,%3}, {%4,%5,%6,%7}, {%8,%9}, {%0,%1,%2,%3};"
                : "+f"(c0), "+f"(c1), "+f"(c2), "+f"(c3)
                : "r"(a4), "r"(a5), "r"(a6), "r"(a7), "r"(b2), "r"(b3));

            const int code0 = codes_s[crow0 + t];
            const int code1 = codes_s[crow1 + t];
            const float2 e0 = *reinterpret_cast<const float2*>(cbs + code0 * CBS_STRIDE + 2 * q);
            const float2 e1 = *reinterpret_cast<const float2*>(cbs + code1 * CBS_STRIDE + 2 * q);
            const float s0 = (t >= tB0) ? sHi0 : sLo0;
            const float s1 = (t >= tB1) ? sHi1 : sLo1;

            // natural-order staging (byte layout == gmem layout within the 64-col chunk)
            const int cc = tt * 8 + 2 * q;
            *reinterpret_cast<float2*>(&ob[rfrag * OB_STRIDE + cc]) =
                make_float2(fmaf(e0.x, s0, c0), fmaf(e0.y, s0, c1));
            *reinterpret_cast<float2*>(&ob[(rfrag + 8) * OB_STRIDE + cc]) =
                make_float2(fmaf(e1.x, s1, c2), fmaf(e1.y, s1, c3));
        }
        __syncwarp();
        asm volatile("fence.proxy.async.shared::cta;" ::: "memory");

        if (lid < 16) {
            float* dst = out + gdst_row + (unsigned)(ch * 64);
            uint32_t src = ob_sm + (uint32_t)(drow * OB_STRIDE * 4);
            asm volatile(
                "cp.async.bulk.global.shared::cta.bulk_group [%0], [%1], 256;"
                :: "l"(dst), "r"(src) : "memory");
        }
        asm volatile("cp.async.bulk.commit_group;" ::: "memory");
    }
    // ensure stores complete before kernel exit
    asm volatile("cp.async.bulk.wait_group 0;" ::: "memory");
}

extern "C" void kernel_launch(void* const* d_in, const int* in_sizes, int n_in,
                              void* d_out, int out_size) {
    const float* codebooks = (const float*)d_in[0];
    const int*   codes     = (const int*)  d_in[1];
    const float* scales    = (const float*)d_in[2];
    const float* L         = (const float*)d_in[3];
    const float* R         = (const float*)d_in[4];
    float*       out       = (float*)d_out;

    cudaFuncSetAttribute(qw_tma_kernel,
                         cudaFuncAttributeMaxDynamicSharedMemorySize, SMEM_TOTAL);

    dim3 grid(COLS / TJ, ROWS / TI);   // (86, 32)
    qw_tma_kernel<<<grid, THREADS, SMEM_TOTAL>>>(codebooks, codes, scales, L, R, out);
}